// round 1
// baseline (speedup 1.0000x reference)
#include <cuda_runtime.h>
#include <cstdint>

// ----------------------------------------------------------------------------
// LatentReasoningModule: encode (H->2L->L) ; 8x GRUCell(L) ; decode (L->2L->H)
// All GEMMs are C[M,N] = A[M,K] @ W[N,K]^T + b, M = 8192.
// tf32 mma.sync tensor-core GEMM, 128x128x32 tiles.
// ----------------------------------------------------------------------------

#define MROWS 8192
#define HDIM  2048
#define LDIM  512

#define BM 128
#define BN 128
#define BK 32
#define SLDS 36   // padded smem stride (floats); (4*grp+qid) bank pattern -> conflict-free

// scratch (device globals; allocation-free per harness rules)
__device__ float g_h1[(size_t)MROWS * 1024];          // encode/decode intermediate (2L)
__device__ float g_lat[(size_t)MROWS * LDIM];         // latent (updated in place)
__device__ float g_gates[(size_t)MROWS * 3072];       // [gi(3L) | gh(3L)] per row

__device__ __forceinline__ float to_tf32(float x) {
    uint32_t u;
    asm("cvt.rna.tf32.f32 %0, %1;" : "=r"(u) : "f"(x));
    return __uint_as_float(u);
}

__device__ __forceinline__ void mma8(float* c, const uint32_t* a, const uint32_t* b) {
    asm volatile(
        "mma.sync.aligned.m16n8k8.row.col.f32.tf32.tf32.f32 "
        "{%0,%1,%2,%3},{%4,%5,%6,%7},{%8,%9},{%0,%1,%2,%3};"
        : "+f"(c[0]), "+f"(c[1]), "+f"(c[2]), "+f"(c[3])
        : "r"(a[0]), "r"(a[1]), "r"(a[2]), "r"(a[3]), "r"(b[0]), "r"(b[1]));
}

// C[M,N] = op(A[M,K] @ B[N,K]^T + bias),  op = relu or identity.
// A row stride lda, B row stride ldb (= K), C row stride ldc.
// Requires: M%128==0, N%128==0, K%32==0, pointers 16B aligned.
__global__ __launch_bounds__(256) void gemm_tf32(
    const float* __restrict__ A, int lda,
    const float* __restrict__ B, int ldb,
    const float* __restrict__ bias,
    float* __restrict__ C, int ldc,
    int K, int do_relu)
{
    __shared__ float sA[BM * SLDS];
    __shared__ float sB[BN * SLDS];

    const int tid  = threadIdx.x;
    const int bm   = blockIdx.y * BM;
    const int bn   = blockIdx.x * BN;
    const int lane = tid & 31;
    const int warp = tid >> 5;
    const int wm   = (warp & 3) * 32;   // warp row offset within block tile
    const int wn   = (warp >> 2) * 64;  // warp col offset
    const int grp  = lane >> 2;         // 0..7
    const int qid  = lane & 3;          // 0..3
    const int lr   = tid >> 3;          // loader row 0..31
    const int lc   = (tid & 7) << 2;    // loader col 0,4..28

    float acc[2][8][4];
#pragma unroll
    for (int i = 0; i < 2; i++)
#pragma unroll
        for (int j = 0; j < 8; j++)
#pragma unroll
            for (int k = 0; k < 4; k++) acc[i][j][k] = 0.f;

    for (int k0 = 0; k0 < K; k0 += BK) {
#pragma unroll
        for (int i = 0; i < 4; i++) {
            int r = i * 32 + lr;
            float4 v = *(const float4*)(A + (size_t)(bm + r) * lda + k0 + lc);
            v.x = to_tf32(v.x); v.y = to_tf32(v.y); v.z = to_tf32(v.z); v.w = to_tf32(v.w);
            *(float4*)(sA + r * SLDS + lc) = v;
        }
#pragma unroll
        for (int i = 0; i < 4; i++) {
            int r = i * 32 + lr;
            float4 v = *(const float4*)(B + (size_t)(bn + r) * ldb + k0 + lc);
            v.x = to_tf32(v.x); v.y = to_tf32(v.y); v.z = to_tf32(v.z); v.w = to_tf32(v.w);
            *(float4*)(sB + r * SLDS + lc) = v;
        }
        __syncthreads();

#pragma unroll
        for (int kk = 0; kk < BK; kk += 8) {
            uint32_t af[2][4], bf[8][2];
#pragma unroll
            for (int mt = 0; mt < 2; mt++) {
                int row = wm + mt * 16 + grp;
                af[mt][0] = __float_as_uint(sA[row * SLDS + kk + qid]);
                af[mt][1] = __float_as_uint(sA[(row + 8) * SLDS + kk + qid]);
                af[mt][2] = __float_as_uint(sA[row * SLDS + kk + qid + 4]);
                af[mt][3] = __float_as_uint(sA[(row + 8) * SLDS + kk + qid + 4]);
            }
#pragma unroll
            for (int nt = 0; nt < 8; nt++) {
                int col = wn + nt * 8 + grp;
                bf[nt][0] = __float_as_uint(sB[col * SLDS + kk + qid]);
                bf[nt][1] = __float_as_uint(sB[col * SLDS + kk + qid + 4]);
            }
#pragma unroll
            for (int mt = 0; mt < 2; mt++)
#pragma unroll
                for (int nt = 0; nt < 8; nt++)
                    mma8(acc[mt][nt], af[mt], bf[nt]);
        }
        __syncthreads();
    }

    // epilogue: bias (+relu), float2 stores
#pragma unroll
    for (int mt = 0; mt < 2; mt++) {
#pragma unroll
        for (int nt = 0; nt < 8; nt++) {
            int colN = bn + wn + nt * 8 + qid * 2;
            int row  = bm + wm + mt * 16 + grp;
            float b0 = bias[colN], b1 = bias[colN + 1];
            float2 v0, v1;
            v0.x = acc[mt][nt][0] + b0;
            v0.y = acc[mt][nt][1] + b1;
            v1.x = acc[mt][nt][2] + b0;
            v1.y = acc[mt][nt][3] + b1;
            if (do_relu) {
                v0.x = fmaxf(v0.x, 0.f); v0.y = fmaxf(v0.y, 0.f);
                v1.x = fmaxf(v1.x, 0.f); v1.y = fmaxf(v1.y, 0.f);
            }
            *(float2*)(C + (size_t)row * ldc + colN)       = v0;
            *(float2*)(C + (size_t)(row + 8) * ldc + colN) = v1;
        }
    }
}

// GRU gate elementwise: reads gates=[gi|gh] and lat, writes new lat (in place)
// and trajectory slice traj[:, :, step, :].
__global__ __launch_bounds__(256) void gru_gate(
    const float* __restrict__ g, float* __restrict__ lat,
    float* __restrict__ traj, int step)
{
    int idx = blockIdx.x * blockDim.x + threadIdx.x;
    if (idx >= MROWS * LDIM) return;
    int row = idx >> 9;        // /512
    int c   = idx & (LDIM - 1);
    const float* gr = g + (size_t)row * 3072;
    float i_r = gr[c], i_z = gr[c + 512], i_n = gr[c + 1024];
    float h_r = gr[c + 1536], h_z = gr[c + 2048], h_n = gr[c + 2560];
    float h = lat[idx];
    float r = 1.f / (1.f + __expf(-(i_r + h_r)));
    float z = 1.f / (1.f + __expf(-(i_z + h_z)));
    float n = tanhf(i_n + r * h_n);
    float out = (1.f - z) * n + z * h;
    lat[idx] = out;
    traj[((size_t)row * 8 + step) * LDIM + c] = out;
}

extern "C" void kernel_launch(void* const* d_in, const int* in_sizes, int n_in,
                              void* d_out, int out_size)
{
    // input order: hidden_states, [num_reasoning_steps], W_enc1, b_enc1, W_enc2,
    // b_enc2, W_dec1, b_dec1, W_dec2, b_dec2, w_ih, w_hh, b_ih, b_hh.
    // Hedge: scalar may or may not be materialized as a device input.
    const int base = (n_in >= 14) ? 2 : 1;
    const float* x      = (const float*)d_in[0];
    const float* W_enc1 = (const float*)d_in[base + 0];
    const float* b_enc1 = (const float*)d_in[base + 1];
    const float* W_enc2 = (const float*)d_in[base + 2];
    const float* b_enc2 = (const float*)d_in[base + 3];
    const float* W_dec1 = (const float*)d_in[base + 4];
    const float* b_dec1 = (const float*)d_in[base + 5];
    const float* W_dec2 = (const float*)d_in[base + 6];
    const float* b_dec2 = (const float*)d_in[base + 7];
    const float* w_ih   = (const float*)d_in[base + 8];
    const float* w_hh   = (const float*)d_in[base + 9];
    const float* b_ih   = (const float*)d_in[base + 10];
    const float* b_hh   = (const float*)d_in[base + 11];

    float* decoded = (float*)d_out;                       // [B,S,H] first
    float* traj    = decoded + (size_t)MROWS * HDIM;      // [B,S,8,L] after

    float *h1, *lat, *gates;
    cudaGetSymbolAddress((void**)&h1, g_h1);
    cudaGetSymbolAddress((void**)&lat, g_lat);
    cudaGetSymbolAddress((void**)&gates, g_gates);

    dim3 blk(256);
    const int gy = MROWS / BM;  // 64

    // encode: h1 = relu(x @ W_enc1^T + b_enc1), lat = h1 @ W_enc2^T + b_enc2
    gemm_tf32<<<dim3(1024 / BN, gy), blk>>>(x, HDIM, W_enc1, HDIM, b_enc1,
                                            h1, 1024, HDIM, 1);
    gemm_tf32<<<dim3(512 / BN, gy), blk>>>(h1, 1024, W_enc2, 1024, b_enc2,
                                           lat, 512, 1024, 0);

    // 8 GRU steps (num_reasoning_steps fixed = 8 by problem setup)
    for (int step = 0; step < 8; step++) {
        gemm_tf32<<<dim3(1536 / BN, gy), blk>>>(lat, 512, w_ih, 512, b_ih,
                                                gates, 3072, 512, 0);
        gemm_tf32<<<dim3(1536 / BN, gy), blk>>>(lat, 512, w_hh, 512, b_hh,
                                                gates + 1536, 3072, 512, 0);
        gru_gate<<<(MROWS * LDIM + 255) / 256, blk>>>(gates, lat, traj, step);
    }

    // decode: h1 = relu(lat @ W_dec1^T + b_dec1), decoded = h1 @ W_dec2^T + b_dec2
    gemm_tf32<<<dim3(1024 / BN, gy), blk>>>(lat, 512, W_dec1, 512, b_dec1,
                                            h1, 1024, 512, 1);
    gemm_tf32<<<dim3(HDIM / BN, gy), blk>>>(h1, 1024, W_dec2, 1024, b_dec2,
                                            decoded, HDIM, 1024, 0);
}

// round 3
// speedup vs baseline: 1.9508x; 1.9508x over previous
#include <cuda_runtime.h>
#include <cuda_fp16.h>
#include <cstdint>

// ----------------------------------------------------------------------------
// LatentReasoningModule, sm_100 legacy tensor-core path (tcgen05 unavailable:
// harness compiles via virtual arch compute_100).
//   fp16 mma.m16n8k16 (fp32 accum), ldmatrix operand loads, 2-stage cp.async.
//   encode: H(2048)->2L(1024) relu ->L(512); 8x GRU(512) fused N=3072; decode.
// GEMM: C[M,N] = op(A[M,K] @ B[N,K]^T + bias), M = 8192.
// Tile: BM=128 BN=128 BK=64, 256 threads (8 warps, each 32x64).
// ----------------------------------------------------------------------------

#define MROWS 8192
#define BM 128
#define BN 128
#define BK 64
#define THREADS 256
#define SROW 144                   // bytes per smem row: 64 halves + 8 pad
#define AB_BYTES (BM * SROW)       // 18432 per operand tile
#define STAGE_BYTES (2 * AB_BYTES) // 36864
#define SMEM_DYN (2 * STAGE_BYTES) // 73728

// ---------------- scratch (device globals; no runtime allocation) ------------
__device__ __half g_xh[(size_t)MROWS * 2048];     // fp16 input
__device__ __half g_h1h[(size_t)MROWS * 1024];    // encode/decode mid (fp16)
__device__ __half g_lath[(size_t)MROWS * 512];    // latent fp16 (GEMM operand)
__device__ float  g_latf[(size_t)MROWS * 512];    // latent fp32 (gate state)
__device__ float  g_gates[(size_t)MROWS * 3072];  // [gi(3L)|gh(3L)] fp32
// fp16 weights, concatenated:
#define OFF_IH    0
#define OFF_HH    786432
#define OFF_ENC1  1572864
#define OFF_ENC2  3670016
#define OFF_DEC1  4194304
#define OFF_DEC2  4718592
__device__ __half g_wh[6815744];
__device__ float  g_bf[3072];                     // concat [b_ih | b_hh]

// ---------------- helpers -----------------------------------------------------
__device__ __forceinline__ uint32_t smem_u32(const void* p) {
    uint32_t a;
    asm("{ .reg .u64 t; cvta.to.shared.u64 t, %1; cvt.u32.u64 %0, t; }"
        : "=r"(a) : "l"(p));
    return a;
}
__device__ __forceinline__ void cp16(uint32_t dst, const void* src) {
    asm volatile("cp.async.cg.shared.global [%0], [%1], 16;"
                 :: "r"(dst), "l"(src));
}
__device__ __forceinline__ void ldsm4(uint32_t* r, uint32_t addr) {
    asm volatile("ldmatrix.sync.aligned.m8n8.x4.shared.b16 {%0,%1,%2,%3}, [%4];"
                 : "=r"(r[0]), "=r"(r[1]), "=r"(r[2]), "=r"(r[3]) : "r"(addr));
}
__device__ __forceinline__ void mma16(float* c, const uint32_t* a, const uint32_t* b) {
    asm volatile(
        "mma.sync.aligned.m16n8k16.row.col.f32.f16.f16.f32 "
        "{%0,%1,%2,%3},{%4,%5,%6,%7},{%8,%9},{%0,%1,%2,%3};"
        : "+f"(c[0]), "+f"(c[1]), "+f"(c[2]), "+f"(c[3])
        : "r"(a[0]), "r"(a[1]), "r"(a[2]), "r"(a[3]), "r"(b[0]), "r"(b[1]));
}

// ---------------- fp16 tensor-core GEMM ---------------------------------------
// Requires M%128==0, N%128==0, K%64==0; A/B rows 16B-aligned.
__global__ __launch_bounds__(THREADS, 2) void gemm_f16(
    const __half* __restrict__ A, int lda,
    const __half* __restrict__ B, int ldb,
    const float* __restrict__ bias,
    float* __restrict__ Cf, __half* __restrict__ Ch, int ldc,
    int K, int do_relu)
{
    extern __shared__ __align__(16) char sm[];
    const uint32_t sbase = smem_u32(sm);

    const int tid  = threadIdx.x;
    const int warp = tid >> 5;
    const int lane = tid & 31;
    const int bm = blockIdx.y * BM;
    const int bn = blockIdx.x * BN;
    const int wm = (warp & 3) * 32;
    const int wn = (warp >> 2) * 64;
    const int grp = lane >> 2;
    const int qid = lane & 3;
    // ldmatrix address patterns
    const int arow = ((lane >> 3) & 1) * 8 + (lane & 7);
    const int acol = ((lane >> 4) & 1) * 8;
    const int brow = ((lane >> 4) & 1) * 8 + (lane & 7);
    const int bcol = ((lane >> 3) & 1) * 8;

    float acc[2][8][4];
#pragma unroll
    for (int i = 0; i < 2; i++)
#pragma unroll
        for (int j = 0; j < 8; j++)
#pragma unroll
            for (int k = 0; k < 4; k++) acc[i][j][k] = 0.f;

    const int niter = K / BK;

    auto load_tile = [&](int it) {
        const int k0 = it * BK;
        const uint32_t sa = sbase + (uint32_t)(it & 1) * STAGE_BYTES;
        const uint32_t sb = sa + AB_BYTES;
        // 128 rows x 8 chunks of 16B each, per operand
#pragma unroll
        for (int t = tid; t < 1024; t += THREADS) {
            int r = t >> 3, c = t & 7;
            cp16(sa + r * SROW + c * 16, A + (size_t)(bm + r) * lda + k0 + c * 8);
        }
#pragma unroll
        for (int t = tid; t < 1024; t += THREADS) {
            int r = t >> 3, c = t & 7;
            cp16(sb + r * SROW + c * 16, B + (size_t)(bn + r) * ldb + k0 + c * 8);
        }
        asm volatile("cp.async.commit_group;" ::: "memory");
    };

    load_tile(0);

    for (int it = 0; it < niter; it++) {
        if (it + 1 < niter) {
            load_tile(it + 1);
            asm volatile("cp.async.wait_group 1;" ::: "memory");
        } else {
            asm volatile("cp.async.wait_group 0;" ::: "memory");
        }
        __syncthreads();

        const uint32_t sa = sbase + (uint32_t)(it & 1) * STAGE_BYTES;
        const uint32_t sb = sa + AB_BYTES;

#pragma unroll
        for (int kk = 0; kk < BK; kk += 16) {
            uint32_t af[2][4], bf[8][2];
#pragma unroll
            for (int mt = 0; mt < 2; mt++)
                ldsm4(af[mt], sa + (wm + mt * 16 + arow) * SROW + (kk + acol) * 2);
#pragma unroll
            for (int np = 0; np < 4; np++) {
                uint32_t r[4];
                ldsm4(r, sb + (wn + np * 16 + brow) * SROW + (kk + bcol) * 2);
                bf[2 * np][0] = r[0]; bf[2 * np][1] = r[1];
                bf[2 * np + 1][0] = r[2]; bf[2 * np + 1][1] = r[3];
            }
#pragma unroll
            for (int mt = 0; mt < 2; mt++)
#pragma unroll
                for (int nt = 0; nt < 8; nt++)
                    mma16(acc[mt][nt], af[mt], bf[nt]);
        }
        __syncthreads();
    }

    // epilogue: bias (+relu), fp32 and/or fp16 stores
#pragma unroll
    for (int mt = 0; mt < 2; mt++) {
#pragma unroll
        for (int nt = 0; nt < 8; nt++) {
            int colN = bn + wn + nt * 8 + qid * 2;
            int row  = bm + wm + mt * 16 + grp;
            float2 bv = *(const float2*)(bias + colN);
            float2 v0, v1;
            v0.x = acc[mt][nt][0] + bv.x; v0.y = acc[mt][nt][1] + bv.y;
            v1.x = acc[mt][nt][2] + bv.x; v1.y = acc[mt][nt][3] + bv.y;
            if (do_relu) {
                v0.x = fmaxf(v0.x, 0.f); v0.y = fmaxf(v0.y, 0.f);
                v1.x = fmaxf(v1.x, 0.f); v1.y = fmaxf(v1.y, 0.f);
            }
            if (Cf) {
                *(float2*)(Cf + (size_t)row * ldc + colN)       = v0;
                *(float2*)(Cf + (size_t)(row + 8) * ldc + colN) = v1;
            }
            if (Ch) {
                *(__half2*)(Ch + (size_t)row * ldc + colN)       = __floats2half2_rn(v0.x, v0.y);
                *(__half2*)(Ch + (size_t)(row + 8) * ldc + colN) = __floats2half2_rn(v1.x, v1.y);
            }
        }
    }
}

// ---------------- elementwise kernels ----------------------------------------
__global__ __launch_bounds__(256) void f2h(const float4* __restrict__ in,
                                           __half2* __restrict__ out, int n4)
{
    int i = blockIdx.x * blockDim.x + threadIdx.x;
    if (i >= n4) return;
    float4 v = in[i];
    out[2 * i]     = __floats2half2_rn(v.x, v.y);
    out[2 * i + 1] = __floats2half2_rn(v.z, v.w);
}

// GRU gates: reads fp32 gates [gi|gh], fp32 lat; writes fp32 lat, fp16 lat, traj.
__global__ __launch_bounds__(256) void gru_gate(
    const float* __restrict__ g, float* __restrict__ latf,
    __half* __restrict__ lath, float* __restrict__ traj, int step)
{
    int idx = blockIdx.x * blockDim.x + threadIdx.x;
    if (idx >= MROWS * 512) return;
    int row = idx >> 9;
    int c   = idx & 511;
    const float* gr = g + (size_t)row * 3072;
    float i_r = gr[c], i_z = gr[c + 512], i_n = gr[c + 1024];
    float h_r = gr[c + 1536], h_z = gr[c + 2048], h_n = gr[c + 2560];
    float h = latf[idx];
    float r = 1.f / (1.f + __expf(-(i_r + h_r)));
    float z = 1.f / (1.f + __expf(-(i_z + h_z)));
    float n = tanhf(i_n + r * h_n);
    float out = (1.f - z) * n + z * h;
    latf[idx] = out;
    lath[idx] = __float2half_rn(out);
    traj[((size_t)row * 8 + step) * 512 + c] = out;
}

// ---------------- launch ------------------------------------------------------
extern "C" void kernel_launch(void* const* d_in, const int* in_sizes, int n_in,
                              void* d_out, int out_size)
{
    const int bse = (n_in >= 14) ? 2 : 1;
    const float* x      = (const float*)d_in[0];
    const float* W_enc1 = (const float*)d_in[bse + 0];
    const float* b_enc1 = (const float*)d_in[bse + 1];
    const float* W_enc2 = (const float*)d_in[bse + 2];
    const float* b_enc2 = (const float*)d_in[bse + 3];
    const float* W_dec1 = (const float*)d_in[bse + 4];
    const float* b_dec1 = (const float*)d_in[bse + 5];
    const float* W_dec2 = (const float*)d_in[bse + 6];
    const float* b_dec2 = (const float*)d_in[bse + 7];
    const float* w_ih   = (const float*)d_in[bse + 8];
    const float* w_hh   = (const float*)d_in[bse + 9];
    const float* b_ih   = (const float*)d_in[bse + 10];
    const float* b_hh   = (const float*)d_in[bse + 11];

    float* decoded = (float*)d_out;
    float* traj    = decoded + (size_t)MROWS * 2048;

    __half *xh, *h1h, *lath, *wh;
    float *latf, *gates, *bf;
    cudaGetSymbolAddress((void**)&xh,    g_xh);
    cudaGetSymbolAddress((void**)&h1h,   g_h1h);
    cudaGetSymbolAddress((void**)&lath,  g_lath);
    cudaGetSymbolAddress((void**)&latf,  g_latf);
    cudaGetSymbolAddress((void**)&gates, g_gates);
    cudaGetSymbolAddress((void**)&wh,    g_wh);
    cudaGetSymbolAddress((void**)&bf,    g_bf);

    cudaFuncSetAttribute(gemm_f16, cudaFuncAttributeMaxDynamicSharedMemorySize,
                         SMEM_DYN);

    // fp32 -> fp16 conversions (weights + input), each call (deterministic)
    auto cvt = [&](const float* src, __half* dst, int n) {
        f2h<<<(n / 4 + 255) / 256, 256>>>((const float4*)src, (__half2*)dst, n / 4);
    };
    cvt(x,      xh,            MROWS * 2048);
    cvt(w_ih,   wh + OFF_IH,   1536 * 512);
    cvt(w_hh,   wh + OFF_HH,   1536 * 512);
    cvt(W_enc1, wh + OFF_ENC1, 1024 * 2048);
    cvt(W_enc2, wh + OFF_ENC2, 512 * 1024);
    cvt(W_dec1, wh + OFF_DEC1, 1024 * 512);
    cvt(W_dec2, wh + OFF_DEC2, 2048 * 1024);
    cudaMemcpyAsync(bf,        b_ih, 1536 * sizeof(float), cudaMemcpyDeviceToDevice);
    cudaMemcpyAsync(bf + 1536, b_hh, 1536 * sizeof(float), cudaMemcpyDeviceToDevice);

    const dim3 blk(THREADS);
    const int gy = MROWS / BM;  // 64

    // encode
    gemm_f16<<<dim3(1024 / BN, gy), blk, SMEM_DYN>>>(
        xh, 2048, wh + OFF_ENC1, 2048, b_enc1, nullptr, h1h, 1024, 2048, 1);
    gemm_f16<<<dim3(512 / BN, gy), blk, SMEM_DYN>>>(
        h1h, 1024, wh + OFF_ENC2, 1024, b_enc2, latf, lath, 512, 1024, 0);

    // 8 GRU steps: fused N=3072 GEMM over concat [w_ih; w_hh], then gates
    for (int step = 0; step < 8; step++) {
        gemm_f16<<<dim3(3072 / BN, gy), blk, SMEM_DYN>>>(
            lath, 512, wh + OFF_IH, 512, bf, gates, nullptr, 3072, 512, 0);
        gru_gate<<<(MROWS * 512 + 255) / 256, 256>>>(gates, latf, lath, traj, step);
    }

    // decode
    gemm_f16<<<dim3(1024 / BN, gy), blk, SMEM_DYN>>>(
        lath, 512, wh + OFF_DEC1, 512, b_dec1, nullptr, h1h, 1024, 512, 1);
    gemm_f16<<<dim3(2048 / BN, gy), blk, SMEM_DYN>>>(
        h1h, 1024, wh + OFF_DEC2, 1024, b_dec2, decoded, nullptr, 2048, 1024, 0);
}